// round 14
// baseline (speedup 1.0000x reference)
#include <cuda_runtime.h>

#define N_ 8
#define C_ 64
#define L_ 512
#define D_ 64
#define TI 16    // rows of i per band block
#define KP 68    // ks smem pitch: multiple of 4 (16B align), conflict-free
#define XP 79    // xb smem pitch: exactly cols 0..78, odd -> conflict-free

// scratch (static device globals — no allocation); 16B-aligned for float4 access
__device__ __align__(16) float g_qb[N_ * L_ * D_];  // q + bh
__device__ __align__(16) float g_kk[N_ * L_ * D_];  // k

// quad barrier: 2 row-pairs (128 threads) share one of the ids 1..8
#define QUAD_BAR(id) asm volatile("bar.sync %0, 128;" :: "r"(id) : "memory")

__device__ __forceinline__ float tanh_hw(float z) {
    float y; asm("tanh.approx.f32 %0, %1;" : "=f"(y) : "f"(z)); return y;
}
__device__ __forceinline__ float ex2_m(float z) {
    float y; asm("ex2.approx.f32 %0, %1;" : "=f"(y) : "f"(z)); return y;
}
__device__ __forceinline__ float rcp_m(float d) {
    float y; asm("rcp.approx.f32 %0, %1;" : "=f"(y) : "f"(d)); return y;
}

// ---------------------------------------------------------------------------
// Kernel 1: q = xt@Wt + bh, k = xt@Wx
// grid (N_, L_/64) = 64 blocks x 1024 threads. W staged ONCE per 64 l-columns
// (4x reuse vs the old 16-l blocks). smem = 16K wt + 16K wx + 16K xs = 48KB.
// ---------------------------------------------------------------------------
__global__ void __launch_bounds__(1024)
proj_kernel(const float* __restrict__ x,
            const float* __restrict__ Wx,
            const float* __restrict__ Wt,
            const float* __restrict__ bh) {
    __shared__ __align__(16) float wt[C_ * D_];
    __shared__ __align__(16) float wx[C_ * D_];
    __shared__ __align__(16) float xs[C_][64];
    int n  = blockIdx.x;
    int l0 = blockIdx.y << 6;
    int t  = threadIdx.x;

    // stage W (1024 float4 each) and x tile (1024 float4, coalesced)
    ((float4*)wt)[t] = ((const float4*)Wt)[t];
    ((float4*)wx)[t] = ((const float4*)Wx)[t];
    {
        int c = t >> 4, l4 = (t & 15) << 2;
        *(float4*)&xs[c][l4] = *(const float4*)(x + (n * C_ + c) * L_ + l0 + l4);
    }
    __syncthreads();

    int dg = t & 15, ll = t >> 4;        // d-group 0..15, l-slot 0..63
    int d0 = dg << 2;
    float q0 = 0, q1 = 0, q2 = 0, q3 = 0, k0 = 0, k1 = 0, k2 = 0, k3 = 0;
#pragma unroll 8
    for (int c = 0; c < C_; c++) {
        float  xv  = xs[c][ll];
        float4 wt4 = *(const float4*)(wt + c * D_ + d0);
        float4 wx4 = *(const float4*)(wx + c * D_ + d0);
        q0 = fmaf(xv, wt4.x, q0); q1 = fmaf(xv, wt4.y, q1);
        q2 = fmaf(xv, wt4.z, q2); q3 = fmaf(xv, wt4.w, q3);
        k0 = fmaf(xv, wx4.x, k0); k1 = fmaf(xv, wx4.y, k1);
        k2 = fmaf(xv, wx4.z, k2); k3 = fmaf(xv, wx4.w, k3);
    }
    float4 b4 = *(const float4*)(bh + d0);
    int gi = (n * L_ + l0 + ll) * D_ + d0;
    float4 qo = { q0 + b4.x, q1 + b4.y, q2 + b4.z, q3 + b4.w };
    float4 ko = { k0, k1, k2, k3 };
    *(float4*)(g_qb + gi) = qo;
    *(float4*)(g_kk + gi) = ko;
}

// ---------------------------------------------------------------------------
// Kernel 2: banded scores + softmax + a + v. TI=16 rows, 2 warps per row.
// grid (N_, L_/TI) = 256 blocks, 1024 threads = 32 warps, 2 blocks/SM.
// v_s transpose staging ALIASES ks (dead after score loop; barrier-guarded).
// Identical to R13 (proven 15.5us).
// ---------------------------------------------------------------------------
__global__ void __launch_bounds__(1024, 2)
band_kernel(const float* __restrict__ x,
            const float* __restrict__ Wa,
            float* __restrict__ out) {
    __shared__ __align__(16) float ks[TI + 63][KP];  // k band tile (21.5KB)
    __shared__ float xb[C_][XP];                     // x band tile (20.2KB)
    __shared__ __align__(16) float qa[TI][64];       // q rows; reused as a rows
    __shared__ __align__(16) float wa_s[D_];
    __shared__ float red_s[TI][2];
    float (*v_s)[TI + 1] = (float (*)[TI + 1]) & ks[0][0];  // alias: v staging

    int n     = blockIdx.x;
    int i0    = blockIdx.y * TI;
    int t     = threadIdx.x;
    int jbase = i0 - 32;

    // --- stage tiles ---
    for (int i4 = t; i4 < (TI + 63) * 16; i4 += 1024) {  // k band, float4
        int jj = i4 >> 4, d4 = (i4 & 15) << 2;
        int gj = jbase + jj;
        float4 v = { 0.f, 0.f, 0.f, 0.f };
        if ((unsigned)gj < (unsigned)L_)
            v = *(const float4*)(g_kk + ((n * L_ + gj) << 6) + d4);
        *(float4*)&ks[jj][d4] = v;
    }
    {   // x band: t -> (c = t>>4, cols (t&15) + 16k)
        int c = t >> 4, cb = t & 15;
        const float* xrow = x + (n * C_ + c) * L_;
#pragma unroll
        for (int k = 0; k < 5; k++) {
            int col = cb + (k << 4);
            if (col < XP) {
                int gj = jbase + col;
                xb[c][col] = ((unsigned)gj < (unsigned)L_) ? xrow[gj] : 0.f;
            }
        }
    }
    if (t < 256) ((float4*)qa)[t] = ((const float4*)(g_qb + (n * L_ + i0) * D_))[t];
    if (t < D_)  wa_s[t] = Wa[t];
    __syncthreads();

    int w = t >> 5, ln = t & 31;
    int w_row = w >> 1, h = w & 1;        // 2 warps per i-row
    int bar_id = 1 + (w_row >> 1);        // 2 row-pairs share a named barrier
    int i   = i0 + w_row;
    int jl  = h * 32 + ln;                // band offset 0..63
    int col = w_row + jl;                 // tile column 0..78
    int gj  = jbase + col;
    bool valid = (unsigned)gj < (unsigned)L_;

    // --- score: acc = sum_d wa_d * tanh(q_d + k_d); 4-way split accumulator ---
    const float* ksr = &ks[col][0];
    const float* qar = &qa[w_row][0];
    float a0 = 0.f, a1 = 0.f, a2 = 0.f, a3 = 0.f;
#pragma unroll
    for (int d4 = 0; d4 < D_; d4 += 4) {
        float4 kv = *(const float4*)(ksr + d4);
        float4 qv = *(const float4*)(qar + d4);
        float4 wv = *(const float4*)(wa_s + d4);
        a0 = fmaf(wv.x, tanh_hw(qv.x + kv.x), a0);
        a1 = fmaf(wv.y, tanh_hw(qv.y + kv.y), a1);
        a2 = fmaf(wv.z, tanh_hw(qv.z + kv.z), a2);
        a3 = fmaf(wv.w, tanh_hw(qv.w + kv.w), a3);
    }
    float acc = (a0 + a1) + (a2 + a3);

    // --- band softmax; no max subtraction (|acc| <= sum|wa|, no overflow;
    //     eps-weight difference vs reference is O(1e-8)) ---
    float e = valid ? ex2_m(acc * 1.442695040888963f) : 0.f;
    float s = e;
#pragma unroll
    for (int o = 16; o > 0; o >>= 1) s += __shfl_xor_sync(0xffffffffu, s, o);
    if (ln == 0) red_s[w_row][h] = s;
    QUAD_BAR(bar_id);
    float S = red_s[w_row][0] + red_s[w_row][1];
    float a = e * rcp_m(S + 1e-6f);
    qa[w_row][jl] = a;                    // q row dead: reuse as a row
    QUAD_BAR(bar_id);

    // --- full a row (stores drain behind later FMA work) ---
    float* arow = out + (size_t)N_ * C_ * L_ + (size_t)(n * L_ + i) * L_;
#pragma unroll
    for (int k = 0; k < 2; k++) {
        int idx = (h * 64 + k * 32 + ln) << 2;    // float index, multiple of 4
        int j0  = idx - i + 32;
        float4 vv;
        vv.x = ((unsigned)(j0)     < 64u) ? qa[w_row][j0]     : 0.f;
        vv.y = ((unsigned)(j0 + 1) < 64u) ? qa[w_row][j0 + 1] : 0.f;
        vv.z = ((unsigned)(j0 + 2) < 64u) ? qa[w_row][j0 + 2] : 0.f;
        vv.w = ((unsigned)(j0 + 3) < 64u) ? qa[w_row][j0 + 3] : 0.f;
        *(float4*)(arow + idx) = vv;
    }

    __syncthreads();   // all ks reads done -> v_s may reuse ks storage

    // --- v[n, c, i]: lane handles c = jl ---
    int c = jl;
    float vacc = 0.f;
#pragma unroll
    for (int j4 = 0; j4 < 64; j4 += 4) {
        float4 av = *(const float4*)(qar + j4);
        vacc = fmaf(av.x, xb[c][w_row + j4],     vacc);
        vacc = fmaf(av.y, xb[c][w_row + j4 + 1], vacc);
        vacc = fmaf(av.z, xb[c][w_row + j4 + 2], vacc);
        vacc = fmaf(av.w, xb[c][w_row + j4 + 3], vacc);
    }
    v_s[c][w_row] = vacc;
    __syncthreads();   // all rows' v_s ready

    // --- coalesced v store via transpose staging ---
    int c2 = t >> 4, il = t & 15;
    out[(n * C_ + c2) * L_ + i0 + il] = v_s[c2][il];
}

// ---------------------------------------------------------------------------
extern "C" void kernel_launch(void* const* d_in, const int* in_sizes, int n_in,
                              void* d_out, int out_size) {
    const float* x  = (const float*)d_in[0];
    const float* Wx = (const float*)d_in[1];
    const float* Wt = (const float*)d_in[2];
    const float* bh = (const float*)d_in[3];
    const float* Wa = (const float*)d_in[4];
    // d_in[5] = ba: cancels in softmax normalization, unused.
    float* out = (float*)d_out;

    proj_kernel<<<dim3(N_, L_ / 64), 1024>>>(x, Wx, Wt, bh);
    band_kernel<<<dim3(N_, L_ / TI), 1024>>>(x, Wa, out);
}

// round 15
// speedup vs baseline: 1.2620x; 1.2620x over previous
#include <cuda_runtime.h>

#define N_ 8
#define C_ 64
#define L_ 512
#define D_ 64
#define TI 16    // rows of i per band block
#define KP 68    // ks smem pitch: multiple of 4 (16B align), conflict-free
#define XP 79    // xb smem pitch: exactly cols 0..78, odd -> conflict-free

// scratch (static device globals — no allocation); 16B-aligned for float4 access
__device__ __align__(16) float g_qb[N_ * L_ * D_];  // q + bh
__device__ __align__(16) float g_kk[N_ * L_ * D_];  // k

// quad barrier: 2 row-pairs (128 threads) share one of the ids 1..8
#define QUAD_BAR(id) asm volatile("bar.sync %0, 128;" :: "r"(id) : "memory")

__device__ __forceinline__ float tanh_hw(float z) {
    float y; asm("tanh.approx.f32 %0, %1;" : "=f"(y) : "f"(z)); return y;
}
__device__ __forceinline__ float ex2_m(float z) {
    float y; asm("ex2.approx.f32 %0, %1;" : "=f"(y) : "f"(z)); return y;
}
__device__ __forceinline__ float rcp_m(float d) {
    float y; asm("rcp.approx.f32 %0, %1;" : "=f"(y) : "f"(d)); return y;
}

// ---------------------------------------------------------------------------
// Kernel 1: q = xt@Wt + bh, k = xt@Wx
// grid (N_, 16) = 128 blocks x 512 threads -> single wave, 16 warps/SM.
// Each block covers 32 l-columns; W staged once per block (41.2KB smem).
// ---------------------------------------------------------------------------
__global__ void __launch_bounds__(512)
proj_kernel(const float* __restrict__ x,
            const float* __restrict__ Wx,
            const float* __restrict__ Wt,
            const float* __restrict__ bh) {
    __shared__ __align__(16) float wt[C_ * D_];       // 16KB
    __shared__ __align__(16) float wx[C_ * D_];       // 16KB
    __shared__ __align__(16) float xs[C_][36];        // 9KB, pitch 36 conflict-free
    int n  = blockIdx.x;
    int l0 = blockIdx.y << 5;
    int t  = threadIdx.x;

    // stage W: 1024 float4 each, 2 iters per thread
    ((float4*)wt)[t]       = ((const float4*)Wt)[t];
    ((float4*)wt)[t + 512] = ((const float4*)Wt)[t + 512];
    ((float4*)wx)[t]       = ((const float4*)Wx)[t];
    ((float4*)wx)[t + 512] = ((const float4*)Wx)[t + 512];
    // stage x tile: 512 float4, one per thread
    {
        int c = t >> 3, l4 = (t & 7) << 2;
        *(float4*)&xs[c][l4] = *(const float4*)(x + (n * C_ + c) * L_ + l0 + l4);
    }
    __syncthreads();

    int dg = t & 15, ll = t >> 4;        // d-group 0..15, l-slot 0..31
    int d0 = dg << 2;
    float q0 = 0, q1 = 0, q2 = 0, q3 = 0, k0 = 0, k1 = 0, k2 = 0, k3 = 0;
#pragma unroll 8
    for (int c = 0; c < C_; c++) {
        float  xv  = xs[c][ll];
        float4 wt4 = *(const float4*)(wt + c * D_ + d0);
        float4 wx4 = *(const float4*)(wx + c * D_ + d0);
        q0 = fmaf(xv, wt4.x, q0); q1 = fmaf(xv, wt4.y, q1);
        q2 = fmaf(xv, wt4.z, q2); q3 = fmaf(xv, wt4.w, q3);
        k0 = fmaf(xv, wx4.x, k0); k1 = fmaf(xv, wx4.y, k1);
        k2 = fmaf(xv, wx4.z, k2); k3 = fmaf(xv, wx4.w, k3);
    }
    float4 b4 = *(const float4*)(bh + d0);
    int gi = (n * L_ + l0 + ll) * D_ + d0;
    float4 qo = { q0 + b4.x, q1 + b4.y, q2 + b4.z, q3 + b4.w };
    float4 ko = { k0, k1, k2, k3 };
    *(float4*)(g_qb + gi) = qo;
    *(float4*)(g_kk + gi) = ko;
}

// ---------------------------------------------------------------------------
// Kernel 2: banded scores + softmax + a + v. TI=16 rows, 2 warps per row.
// grid (N_, L_/TI) = 256 blocks, 1024 threads = 32 warps, 2 blocks/SM.
// v_s transpose staging ALIASES ks (dead after score loop; barrier-guarded).
// Identical to R13 (proven 15.5us).
// ---------------------------------------------------------------------------
__global__ void __launch_bounds__(1024, 2)
band_kernel(const float* __restrict__ x,
            const float* __restrict__ Wa,
            float* __restrict__ out) {
    __shared__ __align__(16) float ks[TI + 63][KP];  // k band tile (21.5KB)
    __shared__ float xb[C_][XP];                     // x band tile (20.2KB)
    __shared__ __align__(16) float qa[TI][64];       // q rows; reused as a rows
    __shared__ __align__(16) float wa_s[D_];
    __shared__ float red_s[TI][2];
    float (*v_s)[TI + 1] = (float (*)[TI + 1]) & ks[0][0];  // alias: v staging

    int n     = blockIdx.x;
    int i0    = blockIdx.y * TI;
    int t     = threadIdx.x;
    int jbase = i0 - 32;

    // --- stage tiles ---
    for (int i4 = t; i4 < (TI + 63) * 16; i4 += 1024) {  // k band, float4
        int jj = i4 >> 4, d4 = (i4 & 15) << 2;
        int gj = jbase + jj;
        float4 v = { 0.f, 0.f, 0.f, 0.f };
        if ((unsigned)gj < (unsigned)L_)
            v = *(const float4*)(g_kk + ((n * L_ + gj) << 6) + d4);
        *(float4*)&ks[jj][d4] = v;
    }
    {   // x band: t -> (c = t>>4, cols (t&15) + 16k)
        int c = t >> 4, cb = t & 15;
        const float* xrow = x + (n * C_ + c) * L_;
#pragma unroll
        for (int k = 0; k < 5; k++) {
            int col = cb + (k << 4);
            if (col < XP) {
                int gj = jbase + col;
                xb[c][col] = ((unsigned)gj < (unsigned)L_) ? xrow[gj] : 0.f;
            }
        }
    }
    if (t < 256) ((float4*)qa)[t] = ((const float4*)(g_qb + (n * L_ + i0) * D_))[t];
    if (t < D_)  wa_s[t] = Wa[t];
    __syncthreads();

    int w = t >> 5, ln = t & 31;
    int w_row = w >> 1, h = w & 1;        // 2 warps per i-row
    int bar_id = 1 + (w_row >> 1);        // 2 row-pairs share a named barrier
    int i   = i0 + w_row;
    int jl  = h * 32 + ln;                // band offset 0..63
    int col = w_row + jl;                 // tile column 0..78
    int gj  = jbase + col;
    bool valid = (unsigned)gj < (unsigned)L_;

    // --- score: acc = sum_d wa_d * tanh(q_d + k_d); 4-way split accumulator ---
    const float* ksr = &ks[col][0];
    const float* qar = &qa[w_row][0];
    float a0 = 0.f, a1 = 0.f, a2 = 0.f, a3 = 0.f;
#pragma unroll
    for (int d4 = 0; d4 < D_; d4 += 4) {
        float4 kv = *(const float4*)(ksr + d4);
        float4 qv = *(const float4*)(qar + d4);
        float4 wv = *(const float4*)(wa_s + d4);
        a0 = fmaf(wv.x, tanh_hw(qv.x + kv.x), a0);
        a1 = fmaf(wv.y, tanh_hw(qv.y + kv.y), a1);
        a2 = fmaf(wv.z, tanh_hw(qv.z + kv.z), a2);
        a3 = fmaf(wv.w, tanh_hw(qv.w + kv.w), a3);
    }
    float acc = (a0 + a1) + (a2 + a3);

    // --- band softmax; no max subtraction (|acc| <= sum|wa|, no overflow;
    //     eps-weight difference vs reference is O(1e-8)) ---
    float e = valid ? ex2_m(acc * 1.442695040888963f) : 0.f;
    float s = e;
#pragma unroll
    for (int o = 16; o > 0; o >>= 1) s += __shfl_xor_sync(0xffffffffu, s, o);
    if (ln == 0) red_s[w_row][h] = s;
    QUAD_BAR(bar_id);
    float S = red_s[w_row][0] + red_s[w_row][1];
    float a = e * rcp_m(S + 1e-6f);
    qa[w_row][jl] = a;                    // q row dead: reuse as a row
    QUAD_BAR(bar_id);

    // --- full a row (stores drain behind later FMA work) ---
    float* arow = out + (size_t)N_ * C_ * L_ + (size_t)(n * L_ + i) * L_;
#pragma unroll
    for (int k = 0; k < 2; k++) {
        int idx = (h * 64 + k * 32 + ln) << 2;    // float index, multiple of 4
        int j0  = idx - i + 32;
        float4 vv;
        vv.x = ((unsigned)(j0)     < 64u) ? qa[w_row][j0]     : 0.f;
        vv.y = ((unsigned)(j0 + 1) < 64u) ? qa[w_row][j0 + 1] : 0.f;
        vv.z = ((unsigned)(j0 + 2) < 64u) ? qa[w_row][j0 + 2] : 0.f;
        vv.w = ((unsigned)(j0 + 3) < 64u) ? qa[w_row][j0 + 3] : 0.f;
        *(float4*)(arow + idx) = vv;
    }

    __syncthreads();   // all ks reads done -> v_s may reuse ks storage

    // --- v[n, c, i]: lane handles c = jl ---
    int c = jl;
    float vacc = 0.f;
#pragma unroll
    for (int j4 = 0; j4 < 64; j4 += 4) {
        float4 av = *(const float4*)(qar + j4);
        vacc = fmaf(av.x, xb[c][w_row + j4],     vacc);
        vacc = fmaf(av.y, xb[c][w_row + j4 + 1], vacc);
        vacc = fmaf(av.z, xb[c][w_row + j4 + 2], vacc);
        vacc = fmaf(av.w, xb[c][w_row + j4 + 3], vacc);
    }
    v_s[c][w_row] = vacc;
    __syncthreads();   // all rows' v_s ready

    // --- coalesced v store via transpose staging ---
    int c2 = t >> 4, il = t & 15;
    out[(n * C_ + c2) * L_ + i0 + il] = v_s[c2][il];
}

// ---------------------------------------------------------------------------
extern "C" void kernel_launch(void* const* d_in, const int* in_sizes, int n_in,
                              void* d_out, int out_size) {
    const float* x  = (const float*)d_in[0];
    const float* Wx = (const float*)d_in[1];
    const float* Wt = (const float*)d_in[2];
    const float* bh = (const float*)d_in[3];
    const float* Wa = (const float*)d_in[4];
    // d_in[5] = ba: cancels in softmax normalization, unused.
    float* out = (float*)d_out;

    proj_kernel<<<dim3(N_, 16), 512>>>(x, Wx, Wt, bh);
    band_kernel<<<dim3(N_, L_ / TI), 1024>>>(x, Wa, out);
}

// round 16
// speedup vs baseline: 1.3935x; 1.1042x over previous
#include <cuda_runtime.h>

#define N_ 8
#define C_ 64
#define L_ 512
#define D_ 64
#define TI 16    // rows of i per band block
#define KP 68    // ks smem pitch: multiple of 4 (16B align), conflict-free
#define XP 79    // xb smem pitch: exactly cols 0..78, odd -> conflict-free

// scratch (static device globals — no allocation); 16B-aligned for float4 access
__device__ __align__(16) float g_qb[N_ * L_ * D_];  // q + bh
__device__ __align__(16) float g_kk[N_ * L_ * D_];  // k

// quad barrier: 2 row-pairs (128 threads) share one of the ids 1..8
#define QUAD_BAR(id) asm volatile("bar.sync %0, 128;" :: "r"(id) : "memory")

__device__ __forceinline__ float tanh_hw(float z) {
    float y; asm("tanh.approx.f32 %0, %1;" : "=f"(y) : "f"(z)); return y;
}
__device__ __forceinline__ float ex2_m(float z) {
    float y; asm("ex2.approx.f32 %0, %1;" : "=f"(y) : "f"(z)); return y;
}
__device__ __forceinline__ float rcp_m(float d) {
    float y; asm("rcp.approx.f32 %0, %1;" : "=f"(y) : "f"(d)); return y;
}

// ---------------------------------------------------------------------------
// Kernel 1: q = xt@Wt + bh, k = xt@Wx
// grid (N_, 16) = 128 blocks x 512 threads, single wave.
// dg = warp index -> W smem reads are BROADCAST (1 wavefront each).
// Signals PDL dependents immediately (consumers sync via griddepcontrol.wait).
// ---------------------------------------------------------------------------
__global__ void __launch_bounds__(512)
proj_kernel(const float* __restrict__ x,
            const float* __restrict__ Wx,
            const float* __restrict__ Wt,
            const float* __restrict__ bh) {
    asm volatile("griddepcontrol.launch_dependents;");
    __shared__ __align__(16) float wt[C_ * D_];       // 16KB
    __shared__ __align__(16) float wx[C_ * D_];       // 16KB
    __shared__ __align__(16) float xs[C_][36];        // 9KB, pitch 36 conflict-free
    int n  = blockIdx.x;
    int l0 = blockIdx.y << 5;
    int t  = threadIdx.x;

    // stage W: 1024 float4 each, 2 iters per thread
    ((float4*)wt)[t]       = ((const float4*)Wt)[t];
    ((float4*)wt)[t + 512] = ((const float4*)Wt)[t + 512];
    ((float4*)wx)[t]       = ((const float4*)Wx)[t];
    ((float4*)wx)[t + 512] = ((const float4*)Wx)[t + 512];
    // stage x tile: 512 float4, one per thread
    {
        int c = t >> 3, l4 = (t & 7) << 2;
        *(float4*)&xs[c][l4] = *(const float4*)(x + (n * C_ + c) * L_ + l0 + l4);
    }
    __syncthreads();

    int dg = t >> 5, ll = t & 31;        // d-group = warp id (uniform), l-slot = lane
    int d0 = dg << 2;
    float q0 = 0, q1 = 0, q2 = 0, q3 = 0, k0 = 0, k1 = 0, k2 = 0, k3 = 0;
#pragma unroll 8
    for (int c = 0; c < C_; c++) {
        float  xv  = xs[c][ll];                            // 1 wf, conflict-free
        float4 wt4 = *(const float4*)(wt + c * D_ + d0);   // warp-broadcast
        float4 wx4 = *(const float4*)(wx + c * D_ + d0);   // warp-broadcast
        q0 = fmaf(xv, wt4.x, q0); q1 = fmaf(xv, wt4.y, q1);
        q2 = fmaf(xv, wt4.z, q2); q3 = fmaf(xv, wt4.w, q3);
        k0 = fmaf(xv, wx4.x, k0); k1 = fmaf(xv, wx4.y, k1);
        k2 = fmaf(xv, wx4.z, k2); k3 = fmaf(xv, wx4.w, k3);
    }
    float4 b4 = *(const float4*)(bh + d0);
    int gi = (n * L_ + l0 + ll) * D_ + d0;
    float4 qo = { q0 + b4.x, q1 + b4.y, q2 + b4.z, q3 + b4.w };
    float4 ko = { k0, k1, k2, k3 };
    *(float4*)(g_qb + gi) = qo;
    *(float4*)(g_kk + gi) = ko;
}

// ---------------------------------------------------------------------------
// Kernel 2: banded scores + softmax + a + v. TI=16 rows, 2 warps per row.
// grid (N_, L_/TI) = 256 blocks, 1024 threads, 2 blocks/SM.
// PDL: xb staging (independent of proj) runs BEFORE griddepcontrol.wait,
// overlapping with proj execution. ks/qa staging after the wait.
// v_s transpose staging ALIASES ks (dead after score loop; barrier-guarded).
// ---------------------------------------------------------------------------
__global__ void __launch_bounds__(1024, 2)
band_kernel(const float* __restrict__ x,
            const float* __restrict__ Wa,
            float* __restrict__ out) {
    __shared__ __align__(16) float ks[TI + 63][KP];  // k band tile (21.5KB)
    __shared__ float xb[C_][XP];                     // x band tile (20.2KB)
    __shared__ __align__(16) float qa[TI][64];       // q rows; reused as a rows
    __shared__ __align__(16) float wa_s[D_];
    __shared__ float red_s[TI][2];
    float (*v_s)[TI + 1] = (float (*)[TI + 1]) & ks[0][0];  // alias: v staging

    int n     = blockIdx.x;
    int i0    = blockIdx.y * TI;
    int t     = threadIdx.x;
    int jbase = i0 - 32;

    // --- stage x band + wa (independent of proj output; overlaps proj) ---
    {
        int c = t >> 4, cb = t & 15;
        const float* xrow = x + (n * C_ + c) * L_;
#pragma unroll
        for (int k = 0; k < 5; k++) {
            int col = cb + (k << 4);
            if (col < XP) {
                int gj = jbase + col;
                xb[c][col] = ((unsigned)gj < (unsigned)L_) ? xrow[gj] : 0.f;
            }
        }
    }
    if (t < D_) wa_s[t] = Wa[t];

    // --- wait for proj's g_kk / g_qb to be visible ---
    asm volatile("griddepcontrol.wait;");

    // --- stage k band + q rows ---
    for (int i4 = t; i4 < (TI + 63) * 16; i4 += 1024) {  // k band, float4
        int jj = i4 >> 4, d4 = (i4 & 15) << 2;
        int gj = jbase + jj;
        float4 v = { 0.f, 0.f, 0.f, 0.f };
        if ((unsigned)gj < (unsigned)L_)
            v = *(const float4*)(g_kk + ((n * L_ + gj) << 6) + d4);
        *(float4*)&ks[jj][d4] = v;
    }
    if (t < 256) ((float4*)qa)[t] = ((const float4*)(g_qb + (n * L_ + i0) * D_))[t];
    __syncthreads();

    int w = t >> 5, ln = t & 31;
    int w_row = w >> 1, h = w & 1;        // 2 warps per i-row
    int bar_id = 1 + (w_row >> 1);        // 2 row-pairs share a named barrier
    int i   = i0 + w_row;
    int jl  = h * 32 + ln;                // band offset 0..63
    int col = w_row + jl;                 // tile column 0..78
    int gj  = jbase + col;
    bool valid = (unsigned)gj < (unsigned)L_;

    // --- score: acc = sum_d wa_d * tanh(q_d + k_d); 4-way split accumulator ---
    const float* ksr = &ks[col][0];
    const float* qar = &qa[w_row][0];
    float a0 = 0.f, a1 = 0.f, a2 = 0.f, a3 = 0.f;
#pragma unroll
    for (int d4 = 0; d4 < D_; d4 += 4) {
        float4 kv = *(const float4*)(ksr + d4);
        float4 qv = *(const float4*)(qar + d4);
        float4 wv = *(const float4*)(wa_s + d4);
        a0 = fmaf(wv.x, tanh_hw(qv.x + kv.x), a0);
        a1 = fmaf(wv.y, tanh_hw(qv.y + kv.y), a1);
        a2 = fmaf(wv.z, tanh_hw(qv.z + kv.z), a2);
        a3 = fmaf(wv.w, tanh_hw(qv.w + kv.w), a3);
    }
    float acc = (a0 + a1) + (a2 + a3);

    // --- band softmax; no max subtraction (|acc| <= sum|wa|, no overflow;
    //     eps-weight difference vs reference is O(1e-8)) ---
    float e = valid ? ex2_m(acc * 1.442695040888963f) : 0.f;
    float s = e;
#pragma unroll
    for (int o = 16; o > 0; o >>= 1) s += __shfl_xor_sync(0xffffffffu, s, o);
    if (ln == 0) red_s[w_row][h] = s;
    QUAD_BAR(bar_id);
    float S = red_s[w_row][0] + red_s[w_row][1];
    float a = e * rcp_m(S + 1e-6f);
    qa[w_row][jl] = a;                    // q row dead: reuse as a row
    QUAD_BAR(bar_id);

    // --- full a row (stores drain behind later FMA work) ---
    float* arow = out + (size_t)N_ * C_ * L_ + (size_t)(n * L_ + i) * L_;
#pragma unroll
    for (int k = 0; k < 2; k++) {
        int idx = (h * 64 + k * 32 + ln) << 2;    // float index, multiple of 4
        int j0  = idx - i + 32;
        float4 vv;
        vv.x = ((unsigned)(j0)     < 64u) ? qa[w_row][j0]     : 0.f;
        vv.y = ((unsigned)(j0 + 1) < 64u) ? qa[w_row][j0 + 1] : 0.f;
        vv.z = ((unsigned)(j0 + 2) < 64u) ? qa[w_row][j0 + 2] : 0.f;
        vv.w = ((unsigned)(j0 + 3) < 64u) ? qa[w_row][j0 + 3] : 0.f;
        *(float4*)(arow + idx) = vv;
    }

    __syncthreads();   // all ks reads done -> v_s may reuse ks storage

    // --- v[n, c, i]: lane handles c = jl ---
    int c = jl;
    float vacc = 0.f;
#pragma unroll
    for (int j4 = 0; j4 < 64; j4 += 4) {
        float4 av = *(const float4*)(qar + j4);
        vacc = fmaf(av.x, xb[c][w_row + j4],     vacc);
        vacc = fmaf(av.y, xb[c][w_row + j4 + 1], vacc);
        vacc = fmaf(av.z, xb[c][w_row + j4 + 2], vacc);
        vacc = fmaf(av.w, xb[c][w_row + j4 + 3], vacc);
    }
    v_s[c][w_row] = vacc;
    __syncthreads();   // all rows' v_s ready

    // --- coalesced v store via transpose staging ---
    int c2 = t >> 4, il = t & 15;
    out[(n * C_ + c2) * L_ + i0 + il] = v_s[c2][il];
}

// ---------------------------------------------------------------------------
extern "C" void kernel_launch(void* const* d_in, const int* in_sizes, int n_in,
                              void* d_out, int out_size) {
    const float* x  = (const float*)d_in[0];
    const float* Wx = (const float*)d_in[1];
    const float* Wt = (const float*)d_in[2];
    const float* bh = (const float*)d_in[3];
    const float* Wa = (const float*)d_in[4];
    // d_in[5] = ba: cancels in softmax normalization, unused.
    float* out = (float*)d_out;

    proj_kernel<<<dim3(N_, 16), 512>>>(x, Wx, Wt, bh);

    // band with Programmatic Dependent Launch: spins up and stages xb while
    // proj is still running; data dependency enforced by griddepcontrol.wait.
    cudaLaunchConfig_t cfg = {};
    cfg.gridDim  = dim3(N_, L_ / TI);
    cfg.blockDim = dim3(1024);
    cfg.dynamicSmemBytes = 0;
    cfg.stream = 0;
    cudaLaunchAttribute attrs[1];
    attrs[0].id = cudaLaunchAttributeProgrammaticStreamSerialization;
    attrs[0].val.programmaticStreamSerializationAllowed = 1;
    cfg.attrs = attrs;
    cfg.numAttrs = 1;
    cudaLaunchKernelEx(&cfg, band_kernel, x, Wa, out);
}